// round 2
// baseline (speedup 1.0000x reference)
#include <cuda_runtime.h>
#include <math.h>
#include <float.h>

// ICP: 20 gated iterations of (lazy-apply + grid 1-NN + Kabsch), then final fit.
// NN uses a uniform spatial hash over the static B cloud (built once per launch).
// Graph-capturable: fixed launch sequence, device-side convergence latch.

#define NPTS 8192
#define MAX_ITERS 20
#define NN_BLOCKS 32            // 32 blocks x 256 threads, 1 thread per src point
#define G 48                    // grid resolution per axis
#define G3 (G*G*G)              // 110592 cells
#define GLO  (-6.0f)
#define GH   (0.25f)            // cell width  (12/48)
#define GINVH (4.0f)            // 1/GH

__device__ float4 g_src4[NPTS];          // current src, w = |p|^2
__device__ float4 g_B4[NPTS];            // B, w = |b|^2
__device__ int    g_cellCnt[G3];         // counts, then scatter cursor
__device__ int    g_cellStart[G3 + 1];
__device__ int    g_cellPnt[NPTS];
__device__ double g_part[NN_BLOCKS][16];
__device__ float  g_T[12];               // R row-major (9) + t (3)
__device__ int    g_done;
__device__ int    g_apply;               // pending-transform flag (lazy apply)
__device__ float  g_prev_err;

__device__ __forceinline__ int cell_of(float x, float y, float z) {
    int cx = (int)floorf((x - GLO) * GINVH);
    int cy = (int)floorf((y - GLO) * GINVH);
    int cz = (int)floorf((z - GLO) * GINVH);
    cx = min(max(cx, 0), G - 1);
    cy = min(max(cy, 0), G - 1);
    cz = min(max(cz, 0), G - 1);
    return (cz * G + cy) * G + cx;
}

// ---------------------------------------------------------------------------
__global__ void k_prep(const float* __restrict__ A, const float* __restrict__ B) {
    int gid = blockIdx.x * blockDim.x + threadIdx.x;
    for (int c = gid; c < G3; c += gridDim.x * blockDim.x) g_cellCnt[c] = 0;
    if (gid < NPTS) {
        float ax = A[3*gid], ay = A[3*gid+1], az = A[3*gid+2];
        g_src4[gid] = make_float4(ax, ay, az, ax*ax + ay*ay + az*az);
        float bx = B[3*gid], by = B[3*gid+1], bz = B[3*gid+2];
        g_B4[gid]   = make_float4(bx, by, bz, bx*bx + by*by + bz*bz);
    }
    if (gid == 0) { g_done = 0; g_apply = 0; g_prev_err = 0.f; }
}

__global__ void k_count() {
    int i = blockIdx.x * blockDim.x + threadIdx.x;
    float4 b = g_B4[i];
    atomicAdd(&g_cellCnt[cell_of(b.x, b.y, b.z)], 1);
}

__global__ void k_scan() {   // 1 block x 1024 threads, 108 cells each
    __shared__ int ssum[1024];
    int t = threadIdx.x;
    int base = t * (G3 / 1024);
    int s = 0;
    for (int i = 0; i < G3 / 1024; ++i) s += g_cellCnt[base + i];
    ssum[t] = s;
    __syncthreads();
    for (int off = 1; off < 1024; off <<= 1) {
        int v = (t >= off) ? ssum[t - off] : 0;
        __syncthreads();
        ssum[t] += v;
        __syncthreads();
    }
    int pre = (t == 0) ? 0 : ssum[t - 1];
    for (int i = 0; i < G3 / 1024; ++i) {
        int c = g_cellCnt[base + i];
        g_cellStart[base + i] = pre;
        pre += c;
        g_cellCnt[base + i] = 0;    // reuse as scatter cursor
    }
    if (t == 1023) g_cellStart[G3] = pre;
}

__global__ void k_scatter() {
    int i = blockIdx.x * blockDim.x + threadIdx.x;
    float4 b = g_B4[i];
    int c = cell_of(b.x, b.y, b.z);
    int pos = atomicAdd(&g_cellCnt[c], 1);
    g_cellPnt[g_cellStart[c] + pos] = i;
}

// ---------------------------------------------------------------------------
// Lazy-apply pending transform, grid 1-NN, per-block partial sums.
__global__ void k_nn() {
    if (g_done) return;
    int tid = threadIdx.x;
    int i = blockIdx.x * 256 + tid;

    float4 s = g_src4[i];
    float sx = s.x, sy = s.y, sz = s.z, ss = s.w;
    if (g_apply) {
        float x = g_T[0]*sx + g_T[1]*sy + g_T[2]*sz + g_T[9];
        float y = g_T[3]*sx + g_T[4]*sy + g_T[5]*sz + g_T[10];
        float z = g_T[6]*sx + g_T[7]*sy + g_T[8]*sz + g_T[11];
        sx = x; sy = y; sz = z;
        ss = sx*sx + sy*sy + sz*sz;
        g_src4[i] = make_float4(sx, sy, sz, ss);   // thread owns point i
    }

    // NN search: d2' = |b|^2 - 2 s.b  (true d2 = d2' + ss)
    float mx = -2.0f*sx, my = -2.0f*sy, mz = -2.0f*sz;
    int cx = min(max((int)floorf((sx - GLO) * GINVH), 0), G - 1);
    int cy = min(max((int)floorf((sy - GLO) * GINVH), 0), G - 1);
    int cz = min(max((int)floorf((sz - GLO) * GINVH), 0), G - 1);
    int rmax = max(max(cx, G-1-cx), max(max(cy, G-1-cy), max(cz, G-1-cz)));

    float best = FLT_MAX;
    int   bj   = 0;
    for (int r = 0; ; ++r) {
        int zlo = max(cz - r, 0), zhi = min(cz + r, G - 1);
        for (int z = zlo; z <= zhi; ++z) {
            int adz = abs(z - cz);
            int ylo = max(cy - r, 0), yhi = min(cy + r, G - 1);
            for (int y = ylo; y <= yhi; ++y) {
                int m = max(adz, abs(y - cy));
                int rowbase = (z * G + y) * G;
                int xlo, xhi;
                if (m == r) { xlo = max(cx - r, 0); xhi = min(cx + r, G - 1); }
                else        { xlo = cx - r;         xhi = cx + r; }
                for (int x = xlo; x <= xhi; x += (m == r ? 1 : (xhi - xlo > 0 ? xhi - xlo : 1))) {
                    if (x < 0 || x >= G) continue;
                    int c = rowbase + x;
                    int k0 = g_cellStart[c], k1 = g_cellStart[c + 1];
                    for (int k = k0; k < k1; ++k) {
                        int j = g_cellPnt[k];
                        float4 b = g_B4[j];
                        float d2 = fmaf(mx, b.x, fmaf(my, b.y, fmaf(mz, b.z, b.w)));
                        if (d2 < best || (d2 == best && j < bj)) { best = d2; bj = j; }
                    }
                    if (m != r && xhi == xlo) break;   // single-column edge case
                }
            }
        }
        float thr = (float)r * GH;
        if (best + ss <= thr * thr) break;
        if (r >= rmax) break;
    }

    // accumulate this point's terms
    float4 b = g_B4[bj];
    double v[16];
    {
        double dsx = sx, dsy = sy, dsz = sz;
        double dbx = b.x, dby = b.y, dbz = b.z;
        v[0] = dsx;  v[1] = dsy;  v[2] = dsz;
        v[3] = dbx;  v[4] = dby;  v[5] = dbz;
        v[6]  = dsx*dbx; v[7]  = dsx*dby; v[8]  = dsx*dbz;
        v[9]  = dsy*dbx; v[10] = dsy*dby; v[11] = dsy*dbz;
        v[12] = dsz*dbx; v[13] = dsz*dby; v[14] = dsz*dbz;
        v[15] = (double)sqrtf(fmaxf(best + ss, 0.0f) + 1e-12f);
    }
    #pragma unroll
    for (int q = 0; q < 16; ++q) {
        #pragma unroll
        for (int off = 16; off > 0; off >>= 1)
            v[q] += __shfl_down_sync(0xffffffffu, v[q], off);
    }
    __shared__ double sm[8][16];
    int warp = tid >> 5, lane = tid & 31;
    if (lane == 0) {
        #pragma unroll
        for (int q = 0; q < 16; ++q) sm[warp][q] = v[q];
    }
    __syncthreads();
    if (tid < 16) {
        double acc = 0.0;
        #pragma unroll
        for (int w = 0; w < 8; ++w) acc += sm[w][tid];
        g_part[blockIdx.x][tid] = acc;
    }
}

// ---------------------------------------------------------------------------
// Final reduce over (A_i, src_i); applies any still-pending transform on read.
__global__ void k_fred(const float* __restrict__ A) {
    int tid = threadIdx.x;
    int i   = blockIdx.x * 256 + tid;
    float4 s = g_src4[i];
    float sx = s.x, sy = s.y, sz = s.z;
    if (g_apply) {
        float x = g_T[0]*sx + g_T[1]*sy + g_T[2]*sz + g_T[9];
        float y = g_T[3]*sx + g_T[4]*sy + g_T[5]*sz + g_T[10];
        float z = g_T[6]*sx + g_T[7]*sy + g_T[8]*sz + g_T[11];
        sx = x; sy = y; sz = z;
    }
    float ax = A[3*i], ay = A[3*i+1], az = A[3*i+2];
    double v[16];
    double pax = ax, pay = ay, paz = az;      // first arg  = A
    double pbx = sx, pby = sy, pbz = sz;      // second arg = src
    v[0] = pax; v[1] = pay; v[2] = paz;
    v[3] = pbx; v[4] = pby; v[5] = pbz;
    v[6]  = pax*pbx; v[7]  = pax*pby; v[8]  = pax*pbz;
    v[9]  = pay*pbx; v[10] = pay*pby; v[11] = pay*pbz;
    v[12] = paz*pbx; v[13] = paz*pby; v[14] = paz*pbz;
    v[15] = 0.0;
    #pragma unroll
    for (int q = 0; q < 16; ++q) {
        #pragma unroll
        for (int off = 16; off > 0; off >>= 1)
            v[q] += __shfl_down_sync(0xffffffffu, v[q], off);
    }
    __shared__ double sm[8][16];
    int warp = tid >> 5, lane = tid & 31;
    if (lane == 0) {
        #pragma unroll
        for (int q = 0; q < 16; ++q) sm[warp][q] = v[q];
    }
    __syncthreads();
    if (tid < 16) {
        double acc = 0.0;
        #pragma unroll
        for (int w = 0; w < 8; ++w) acc += sm[w][tid];
        g_part[blockIdx.x][tid] = acc;
    }
}

// ---------------------------------------------------------------------------
__device__ void kabsch3(const float H[9], const float cA[3], const float cB[3],
                        float R[9], float t[3]) {
    float K[3][3], V[3][3];
    #pragma unroll
    for (int i = 0; i < 3; ++i)
        #pragma unroll
        for (int j = 0; j < 3; ++j) {
            K[i][j] = H[0+i]*H[0+j] + H[3+i]*H[3+j] + H[6+i]*H[6+j];
            V[i][j] = (i == j) ? 1.0f : 0.0f;
        }
    const int pq[3][2] = {{0,1},{0,2},{1,2}};
    for (int sw = 0; sw < 8; ++sw) {
        for (int r3 = 0; r3 < 3; ++r3) {
            int p = pq[r3][0], q = pq[r3][1];
            float apq = K[p][q];
            if (fabsf(apq) < 1e-25f) continue;
            float theta = (K[q][q] - K[p][p]) / (2.0f * apq);
            float tt = 1.0f / (fabsf(theta) + sqrtf(theta*theta + 1.0f));
            if (theta < 0.0f) tt = -tt;
            float c = rsqrtf(tt*tt + 1.0f);
            float s = tt * c;
            #pragma unroll
            for (int r = 0; r < 3; ++r) {
                float kp = K[r][p], kq = K[r][q];
                K[r][p] = c*kp - s*kq; K[r][q] = s*kp + c*kq;
            }
            #pragma unroll
            for (int cc = 0; cc < 3; ++cc) {
                float kp = K[p][cc], kq = K[q][cc];
                K[p][cc] = c*kp - s*kq; K[q][cc] = s*kp + c*kq;
            }
            #pragma unroll
            for (int r = 0; r < 3; ++r) {
                float vp = V[r][p], vq = V[r][q];
                V[r][p] = c*vp - s*vq; V[r][q] = s*vp + c*vq;
            }
        }
    }
    float lam[3] = {K[0][0], K[1][1], K[2][2]};
    int ord[3] = {0, 1, 2};
    #pragma unroll
    for (int a = 0; a < 2; ++a)
        #pragma unroll
        for (int b = 0; b < 2 - a; ++b)
            if (lam[ord[b]] < lam[ord[b+1]]) { int tmp = ord[b]; ord[b] = ord[b+1]; ord[b+1] = tmp; }
    float Vs[3][3];
    #pragma unroll
    for (int k = 0; k < 3; ++k)
        #pragma unroll
        for (int r = 0; r < 3; ++r) Vs[r][k] = V[r][ord[k]];

    float U[3][3], sig[3];
    #pragma unroll
    for (int k = 0; k < 3; ++k) {
        float u0 = H[0]*Vs[0][k] + H[1]*Vs[1][k] + H[2]*Vs[2][k];
        float u1 = H[3]*Vs[0][k] + H[4]*Vs[1][k] + H[5]*Vs[2][k];
        float u2 = H[6]*Vs[0][k] + H[7]*Vs[1][k] + H[8]*Vs[2][k];
        float n = sqrtf(u0*u0 + u1*u1 + u2*u2);
        sig[k] = n;
        float inv = (n > 1e-25f) ? 1.0f / n : 0.0f;
        U[0][k] = u0*inv; U[1][k] = u1*inv; U[2][k] = u2*inv;
    }
    if (sig[2] <= 1e-10f * sig[0]) {
        float u0 = U[1][0]*U[2][1] - U[2][0]*U[1][1];
        float u1 = U[2][0]*U[0][1] - U[0][0]*U[2][1];
        float u2 = U[0][0]*U[1][1] - U[1][0]*U[0][1];
        float n = rsqrtf(fmaxf(u0*u0 + u1*u1 + u2*u2, 1e-30f));
        U[0][2] = u0*n; U[1][2] = u1*n; U[2][2] = u2*n;
    }
    float R0[3][3];
    #pragma unroll
    for (int i = 0; i < 3; ++i)
        #pragma unroll
        for (int j = 0; j < 3; ++j)
            R0[i][j] = Vs[i][0]*U[j][0] + Vs[i][1]*U[j][1] + Vs[i][2]*U[j][2];
    float det = R0[0][0]*(R0[1][1]*R0[2][2] - R0[1][2]*R0[2][1])
              - R0[0][1]*(R0[1][0]*R0[2][2] - R0[1][2]*R0[2][0])
              + R0[0][2]*(R0[1][0]*R0[2][1] - R0[1][1]*R0[2][0]);
    if (det < 0.0f) {
        #pragma unroll
        for (int i = 0; i < 3; ++i) Vs[i][2] = -Vs[i][2];
        #pragma unroll
        for (int i = 0; i < 3; ++i)
            #pragma unroll
            for (int j = 0; j < 3; ++j)
                R0[i][j] = Vs[i][0]*U[j][0] + Vs[i][1]*U[j][1] + Vs[i][2]*U[j][2];
    }
    #pragma unroll
    for (int i = 0; i < 3; ++i) {
        #pragma unroll
        for (int j = 0; j < 3; ++j) R[i*3+j] = R0[i][j];
        t[i] = cB[i] - (R0[i][0]*cA[0] + R0[i][1]*cA[1] + R0[i][2]*cA[2]);
    }
}

// ---------------------------------------------------------------------------
__global__ void k_solve(int nrows, int final_pass, float* out) {
    int tid = threadIdx.x;
    double v[16];
    #pragma unroll
    for (int q = 0; q < 16; ++q)
        v[q] = (tid < nrows) ? g_part[tid][q] : 0.0;
    #pragma unroll
    for (int q = 0; q < 16; ++q) {
        #pragma unroll
        for (int off = 16; off > 0; off >>= 1)
            v[q] += __shfl_down_sync(0xffffffffu, v[q], off);
    }
    __shared__ double sm[4][16];
    int warp = tid >> 5, lane = tid & 31;
    if (lane == 0) {
        #pragma unroll
        for (int q = 0; q < 16; ++q) sm[warp][q] = v[q];
    }
    __syncthreads();
    if (tid != 0) return;

    // if latched, leave pending g_T/g_apply untouched for k_fred
    if (!final_pass && g_done) return;

    double S[16];
    #pragma unroll
    for (int q = 0; q < 16; ++q)
        S[q] = sm[0][q] + sm[1][q] + sm[2][q] + sm[3][q];

    const double N = (double)NPTS;
    double cAd[3] = {S[0]/N, S[1]/N, S[2]/N};
    double cBd[3] = {S[3]/N, S[4]/N, S[5]/N};
    float H[9], cA[3], cB[3];
    #pragma unroll
    for (int r = 0; r < 3; ++r) {
        cA[r] = (float)cAd[r]; cB[r] = (float)cBd[r];
        #pragma unroll
        for (int c = 0; c < 3; ++c)
            H[r*3+c] = (float)(S[6 + 3*r + c]/N - cAd[r]*cBd[c]);
    }
    float R[9], t[3];
    kabsch3(H, cA, cB, R, t);

    if (final_pass) {
        #pragma unroll
        for (int r = 0; r < 3; ++r) {
            out[r*4+0] = R[r*3+0]; out[r*4+1] = R[r*3+1];
            out[r*4+2] = R[r*3+2]; out[r*4+3] = t[r];
        }
        out[12] = 0.f; out[13] = 0.f; out[14] = 0.f; out[15] = 1.f;
    } else {
        #pragma unroll
        for (int q = 0; q < 9; ++q) g_T[q] = R[q];
        g_T[9] = t[0]; g_T[10] = t[1]; g_T[11] = t[2];
        float errf = (float)(S[15] / N);
        int conv = fabsf(g_prev_err - errf) < 1e-3f;
        g_prev_err = errf;
        g_apply = 1;               // pending; applied by next k_nn or by k_fred
        if (conv) g_done = 1;
    }
}

// ---------------------------------------------------------------------------
extern "C" void kernel_launch(void* const* d_in, const int* in_sizes, int n_in,
                              void* d_out, int out_size) {
    const float* A = (const float*)d_in[0];
    const float* B = (const float*)d_in[1];
    float* out = (float*)d_out;

    k_prep<<<(G3 + 255) / 256, 256>>>(A, B);
    k_count<<<NPTS / 256, 256>>>();
    k_scan<<<1, 1024>>>();
    k_scatter<<<NPTS / 256, 256>>>();
    for (int it = 0; it < MAX_ITERS; ++it) {
        k_nn<<<NN_BLOCKS, 256>>>();
        k_solve<<<1, 128>>>(NN_BLOCKS, 0, nullptr);
    }
    k_fred<<<NN_BLOCKS, 256>>>(A);
    k_solve<<<1, 128>>>(NN_BLOCKS, 1, out);
}

// round 3
// speedup vs baseline: 3.1991x; 3.1991x over previous
#include <cuda_runtime.h>
#include <math.h>
#include <float.h>

// ICP: brute-force 1-NN with packed f32x2 FMA + FMNMX-only inner loop,
// chunk-rescan argmin recovery, fused last-block Kabsch solve, lazy apply.
// Graph-capturable: fixed launch sequence, device-side convergence latch.

#define NPTS 8192
#define NQ   (NPTS / 4)          // 2048 quads
#define MAX_ITERS 20
#define NN_BLOCKS 256
#define NN_TPB 256               // 65536 threads, 8 partitions per src point
#define STEPS 256                // quads per thread
#define CHUNKS 16
#define CSTEPS 16                // steps per chunk (64 points)
#define FR_BLOCKS 32

typedef unsigned long long ull;

__device__ float4     g_src4[NPTS];     // current src, w = |p|^2
__device__ float4     g_B4[NPTS];       // B AoS (for argmin fetch), w = |b|^2
__device__ ulonglong2 g_Bx[NQ];         // SoA: packed (x0,x1),(x2,x3) per quad
__device__ ulonglong2 g_By[NQ];
__device__ ulonglong2 g_Bz[NQ];
__device__ ulonglong2 g_Bw[NQ];         // |b|^2
__device__ double     g_part[NN_BLOCKS][16];
__device__ float      g_T[12];          // R row-major (9) + t (3)
__device__ int        g_done, g_apply, g_cnt;
__device__ float      g_prev_err;

__device__ __forceinline__ ull pk2(float lo, float hi) {
    ull r; asm("mov.b64 %0,{%1,%2};" : "=l"(r) : "f"(lo), "f"(hi)); return r;
}
__device__ __forceinline__ ull fma2(ull a, ull b, ull c) {
    ull d; asm("fma.rn.f32x2 %0,%1,%2,%3;" : "=l"(d) : "l"(a), "l"(b), "l"(c)); return d;
}
__device__ __forceinline__ void upk2(ull v, float& lo, float& hi) {
    asm("mov.b64 {%0,%1},%2;" : "=f"(lo), "=f"(hi) : "l"(v));
}

// ---------------------------------------------------------------------------
__global__ void k_prep(const float* __restrict__ A, const float* __restrict__ B) {
    int gid = blockIdx.x * blockDim.x + threadIdx.x;
    if (gid < NPTS) {
        float ax = A[3*gid], ay = A[3*gid+1], az = A[3*gid+2];
        g_src4[gid] = make_float4(ax, ay, az, ax*ax + ay*ay + az*az);
        float bx = B[3*gid], by = B[3*gid+1], bz = B[3*gid+2];
        g_B4[gid]   = make_float4(bx, by, bz, bx*bx + by*by + bz*bz);
    }
    if (gid < NQ) {
        const float4* B4 = (const float4*)B;
        float4 f0 = B4[3*gid], f1 = B4[3*gid+1], f2 = B4[3*gid+2];
        float x0=f0.x, y0=f0.y, z0=f0.z;
        float x1=f0.w, y1=f1.x, z1=f1.y;
        float x2=f1.z, y2=f1.w, z2=f2.x;
        float x3=f2.y, y3=f2.z, z3=f2.w;
        ((float4*)g_Bx)[gid] = make_float4(x0, x1, x2, x3);
        ((float4*)g_By)[gid] = make_float4(y0, y1, y2, y3);
        ((float4*)g_Bz)[gid] = make_float4(z0, z1, z2, z3);
        ((float4*)g_Bw)[gid] = make_float4(x0*x0+y0*y0+z0*z0, x1*x1+y1*y1+z1*z1,
                                           x2*x2+y2*y2+z2*z2, x3*x3+y3*y3+z3*z3);
    }
    if (gid == 0) { g_done = 0; g_apply = 0; g_prev_err = 0.f; g_cnt = 0; }
}

// ---------------------------------------------------------------------------
__device__ void kabsch3(const float H[9], const float cA[3], const float cB[3],
                        float R[9], float t[3]) {
    float K[3][3], V[3][3];
    #pragma unroll
    for (int i = 0; i < 3; ++i)
        #pragma unroll
        for (int j = 0; j < 3; ++j) {
            K[i][j] = H[0+i]*H[0+j] + H[3+i]*H[3+j] + H[6+i]*H[6+j];
            V[i][j] = (i == j) ? 1.0f : 0.0f;
        }
    const int pq[3][2] = {{0,1},{0,2},{1,2}};
    for (int sw = 0; sw < 8; ++sw) {
        for (int r3 = 0; r3 < 3; ++r3) {
            int p = pq[r3][0], q = pq[r3][1];
            float apq = K[p][q];
            if (fabsf(apq) < 1e-25f) continue;
            float theta = (K[q][q] - K[p][p]) / (2.0f * apq);
            float tt = 1.0f / (fabsf(theta) + sqrtf(theta*theta + 1.0f));
            if (theta < 0.0f) tt = -tt;
            float c = rsqrtf(tt*tt + 1.0f);
            float s = tt * c;
            #pragma unroll
            for (int r = 0; r < 3; ++r) {
                float kp = K[r][p], kq = K[r][q];
                K[r][p] = c*kp - s*kq; K[r][q] = s*kp + c*kq;
            }
            #pragma unroll
            for (int cc = 0; cc < 3; ++cc) {
                float kp = K[p][cc], kq = K[q][cc];
                K[p][cc] = c*kp - s*kq; K[q][cc] = s*kp + c*kq;
            }
            #pragma unroll
            for (int r = 0; r < 3; ++r) {
                float vp = V[r][p], vq = V[r][q];
                V[r][p] = c*vp - s*vq; V[r][q] = s*vp + c*vq;
            }
        }
    }
    float lam[3] = {K[0][0], K[1][1], K[2][2]};
    int ord[3] = {0, 1, 2};
    #pragma unroll
    for (int a = 0; a < 2; ++a)
        #pragma unroll
        for (int b = 0; b < 2 - a; ++b)
            if (lam[ord[b]] < lam[ord[b+1]]) { int tmp = ord[b]; ord[b] = ord[b+1]; ord[b+1] = tmp; }
    float Vs[3][3];
    #pragma unroll
    for (int k = 0; k < 3; ++k)
        #pragma unroll
        for (int r = 0; r < 3; ++r) Vs[r][k] = V[r][ord[k]];

    float U[3][3], sig[3];
    #pragma unroll
    for (int k = 0; k < 3; ++k) {
        float u0 = H[0]*Vs[0][k] + H[1]*Vs[1][k] + H[2]*Vs[2][k];
        float u1 = H[3]*Vs[0][k] + H[4]*Vs[1][k] + H[5]*Vs[2][k];
        float u2 = H[6]*Vs[0][k] + H[7]*Vs[1][k] + H[8]*Vs[2][k];
        float n = sqrtf(u0*u0 + u1*u1 + u2*u2);
        sig[k] = n;
        float inv = (n > 1e-25f) ? 1.0f / n : 0.0f;
        U[0][k] = u0*inv; U[1][k] = u1*inv; U[2][k] = u2*inv;
    }
    if (sig[2] <= 1e-10f * sig[0]) {
        float u0 = U[1][0]*U[2][1] - U[2][0]*U[1][1];
        float u1 = U[2][0]*U[0][1] - U[0][0]*U[2][1];
        float u2 = U[0][0]*U[1][1] - U[1][0]*U[0][1];
        float n = rsqrtf(fmaxf(u0*u0 + u1*u1 + u2*u2, 1e-30f));
        U[0][2] = u0*n; U[1][2] = u1*n; U[2][2] = u2*n;
    }
    float R0[3][3];
    #pragma unroll
    for (int i = 0; i < 3; ++i)
        #pragma unroll
        for (int j = 0; j < 3; ++j)
            R0[i][j] = Vs[i][0]*U[j][0] + Vs[i][1]*U[j][1] + Vs[i][2]*U[j][2];
    float det = R0[0][0]*(R0[1][1]*R0[2][2] - R0[1][2]*R0[2][1])
              - R0[0][1]*(R0[1][0]*R0[2][2] - R0[1][2]*R0[2][0])
              + R0[0][2]*(R0[1][0]*R0[2][1] - R0[1][1]*R0[2][0]);
    if (det < 0.0f) {
        #pragma unroll
        for (int i = 0; i < 3; ++i) Vs[i][2] = -Vs[i][2];
        #pragma unroll
        for (int i = 0; i < 3; ++i)
            #pragma unroll
            for (int j = 0; j < 3; ++j)
                R0[i][j] = Vs[i][0]*U[j][0] + Vs[i][1]*U[j][1] + Vs[i][2]*U[j][2];
    }
    #pragma unroll
    for (int i = 0; i < 3; ++i) {
        #pragma unroll
        for (int j = 0; j < 3; ++j) R[i*3+j] = R0[i][j];
        t[i] = cB[i] - (R0[i][0]*cA[0] + R0[i][1]*cA[1] + R0[i][2]*cA[2]);
    }
}

// solve from S[16] (full sums); iteration path writes latch state.
__device__ void solve_iter(const double S[16]) {
    const double N = (double)NPTS;
    double cAd[3] = {S[0]/N, S[1]/N, S[2]/N};
    double cBd[3] = {S[3]/N, S[4]/N, S[5]/N};
    float H[9], cA[3], cB[3];
    #pragma unroll
    for (int r = 0; r < 3; ++r) {
        cA[r] = (float)cAd[r]; cB[r] = (float)cBd[r];
        #pragma unroll
        for (int c = 0; c < 3; ++c)
            H[r*3+c] = (float)(S[6 + 3*r + c]/N - cAd[r]*cBd[c]);
    }
    float R[9], t[3];
    kabsch3(H, cA, cB, R, t);
    #pragma unroll
    for (int q = 0; q < 9; ++q) g_T[q] = R[q];
    g_T[9] = t[0]; g_T[10] = t[1]; g_T[11] = t[2];
    float errf = (float)(S[15] / N);
    int conv = fabsf(g_prev_err - errf) < 1e-3f;
    g_prev_err = errf;
    g_apply = 1;                 // pending; applied by next k_nn or by k_fred
    if (conv) g_done = 1;
}

// ---------------------------------------------------------------------------
// NN + block reduce + last-block Kabsch solve, all in one kernel.
__global__ void __launch_bounds__(NN_TPB) k_nn() {
    if (g_done) return;
    int tid  = threadIdx.x;
    int gt   = blockIdx.x * NN_TPB + tid;
    int i    = gt >> 3;          // src point
    int part = gt & 7;           // partition (stride-8 quad interleave)

    float4 s = g_src4[i];
    float sx = s.x, sy = s.y, sz = s.z;
    if (g_apply) {
        float x = g_T[0]*sx + g_T[1]*sy + g_T[2]*sz + g_T[9];
        float y = g_T[3]*sx + g_T[4]*sy + g_T[5]*sz + g_T[10];
        float z = g_T[6]*sx + g_T[7]*sy + g_T[8]*sz + g_T[11];
        sx = x; sy = y; sz = z;
        if (part == 0) g_src4[i] = make_float4(sx, sy, sz, sx*sx + sy*sy + sz*sz);
    }

    // d2' = |b|^2 - 2 s.b   (true d2 = d2' + ss; ordering identical per thread)
    ull mx2 = pk2(-2.f*sx, -2.f*sx);
    ull my2 = pk2(-2.f*sy, -2.f*sy);
    ull mz2 = pk2(-2.f*sz, -2.f*sz);

    float b0 = FLT_MAX, b1 = FLT_MAX, b2 = FLT_MAX, b3 = FLT_MAX;
    float gbest = FLT_MAX;
    int   cbest = 0;
    int   q = part;
    for (int c = 0; c < CHUNKS; ++c) {
        #pragma unroll 4
        for (int kk = 0; kk < CSTEPS; ++kk) {
            ulonglong2 xv = g_Bx[q], yv = g_By[q], zv = g_Bz[q], wv = g_Bw[q];
            ull t01 = fma2(zv.x, mz2, wv.x);
            t01 = fma2(yv.x, my2, t01);
            t01 = fma2(xv.x, mx2, t01);
            ull t23 = fma2(zv.y, mz2, wv.y);
            t23 = fma2(yv.y, my2, t23);
            t23 = fma2(xv.y, mx2, t23);
            float f0, f1, f2, f3;
            upk2(t01, f0, f1); upk2(t23, f2, f3);
            b0 = fminf(b0, f0); b1 = fminf(b1, f1);
            b2 = fminf(b2, f2); b3 = fminf(b3, f3);
            q += 8;
        }
        float m = fminf(fminf(b0, b1), fminf(b2, b3));
        if (m < gbest) { gbest = m; cbest = c; }
    }

    // rescan the last-improving chunk for the argmin index (bit-exact recompute)
    int bj = NPTS - 1;
    {
        int qq = part + 8 * (cbest * CSTEPS);
        for (int kk = 0; kk < CSTEPS; ++kk) {
            ulonglong2 xv = g_Bx[qq], yv = g_By[qq], zv = g_Bz[qq], wv = g_Bw[qq];
            ull t01 = fma2(zv.x, mz2, wv.x);
            t01 = fma2(yv.x, my2, t01);
            t01 = fma2(xv.x, mx2, t01);
            ull t23 = fma2(zv.y, mz2, wv.y);
            t23 = fma2(yv.y, my2, t23);
            t23 = fma2(xv.y, mx2, t23);
            float f0, f1, f2, f3;
            upk2(t01, f0, f1); upk2(t23, f2, f3);
            int j0 = 4 * qq;
            if (f3 == gbest) bj = min(bj, j0 + 3);
            if (f2 == gbest) bj = min(bj, j0 + 2);
            if (f1 == gbest) bj = min(bj, j0 + 1);
            if (f0 == gbest) bj = min(bj, j0 + 0);
            qq += 8;
        }
    }

    // combine the 8 partitions (lexicographic min on (d2', j))
    float best = gbest;
    #pragma unroll
    for (int off = 1; off < 8; off <<= 1) {
        float od = __shfl_xor_sync(0xffffffffu, best, off);
        int   oj = __shfl_xor_sync(0xffffffffu, bj,   off);
        if (od < best || (od == best && oj < bj)) { best = od; bj = oj; }
    }

    // per-point accumulation terms (identical on all 8 lanes of a group)
    float4 b = g_B4[bj];
    float ss = sx*sx + sy*sy + sz*sz;
    double v[16];
    {
        double dsx = sx, dsy = sy, dsz = sz;
        double dbx = b.x, dby = b.y, dbz = b.z;
        v[0] = dsx;  v[1] = dsy;  v[2] = dsz;
        v[3] = dbx;  v[4] = dby;  v[5] = dbz;
        v[6]  = dsx*dbx; v[7]  = dsx*dby; v[8]  = dsx*dbz;
        v[9]  = dsy*dbx; v[10] = dsy*dby; v[11] = dsy*dbz;
        v[12] = dsz*dbx; v[13] = dsz*dby; v[14] = dsz*dbz;
        v[15] = (double)sqrtf(fmaxf(best + ss, 0.0f) + 1e-12f);
    }
    // sum the 4 src points per warp (lanes 0,8,16,24; groups are replicated)
    #pragma unroll
    for (int qi = 0; qi < 16; ++qi) {
        v[qi] += __shfl_xor_sync(0xffffffffu, v[qi], 8);
        v[qi] += __shfl_xor_sync(0xffffffffu, v[qi], 16);
    }

    __shared__ double sm[8][16];
    __shared__ int slast;
    int warp = tid >> 5, lane = tid & 31;
    if (lane == 0) {
        #pragma unroll
        for (int qi = 0; qi < 16; ++qi) sm[warp][qi] = v[qi];
    }
    __syncthreads();
    if (tid < 16) {
        double acc = 0.0;
        #pragma unroll
        for (int w = 0; w < 8; ++w) acc += sm[w][tid];
        g_part[blockIdx.x][tid] = acc;
    }
    __syncthreads();
    __threadfence();
    if (tid == 0) slast = (atomicAdd(&g_cnt, 1) == gridDim.x - 1);
    __syncthreads();
    if (!slast) return;

    // --- last block: reduce all 256 block partials and solve ---
    double w[16];
    #pragma unroll
    for (int qi = 0; qi < 16; ++qi) w[qi] = g_part[tid][qi];
    #pragma unroll
    for (int qi = 0; qi < 16; ++qi) {
        #pragma unroll
        for (int off = 16; off > 0; off >>= 1)
            w[qi] += __shfl_down_sync(0xffffffffu, w[qi], off);
    }
    __syncthreads();            // sm reuse
    if (lane == 0) {
        #pragma unroll
        for (int qi = 0; qi < 16; ++qi) sm[warp][qi] = w[qi];
    }
    __syncthreads();
    if (tid == 0) {
        double S[16];
        #pragma unroll
        for (int qi = 0; qi < 16; ++qi)
            S[qi] = sm[0][qi] + sm[1][qi] + sm[2][qi] + sm[3][qi]
                  + sm[4][qi] + sm[5][qi] + sm[6][qi] + sm[7][qi];
        solve_iter(S);
        g_cnt = 0;              // rearm for next launch / graph replay
    }
}

// ---------------------------------------------------------------------------
// Final reduce over (A_i, src_i); applies any still-pending transform on read.
__global__ void k_fred(const float* __restrict__ A) {
    int tid = threadIdx.x;
    int i   = blockIdx.x * 256 + tid;
    float4 s = g_src4[i];
    float sx = s.x, sy = s.y, sz = s.z;
    if (g_apply) {
        float x = g_T[0]*sx + g_T[1]*sy + g_T[2]*sz + g_T[9];
        float y = g_T[3]*sx + g_T[4]*sy + g_T[5]*sz + g_T[10];
        float z = g_T[6]*sx + g_T[7]*sy + g_T[8]*sz + g_T[11];
        sx = x; sy = y; sz = z;
    }
    float ax = A[3*i], ay = A[3*i+1], az = A[3*i+2];
    double v[16];
    double pax = ax, pay = ay, paz = az;      // first arg  = A
    double pbx = sx, pby = sy, pbz = sz;      // second arg = src
    v[0] = pax; v[1] = pay; v[2] = paz;
    v[3] = pbx; v[4] = pby; v[5] = pbz;
    v[6]  = pax*pbx; v[7]  = pax*pby; v[8]  = pax*pbz;
    v[9]  = pay*pbx; v[10] = pay*pby; v[11] = pay*pbz;
    v[12] = paz*pbx; v[13] = paz*pby; v[14] = paz*pbz;
    v[15] = 0.0;
    #pragma unroll
    for (int qi = 0; qi < 16; ++qi) {
        #pragma unroll
        for (int off = 16; off > 0; off >>= 1)
            v[qi] += __shfl_down_sync(0xffffffffu, v[qi], off);
    }
    __shared__ double sm[8][16];
    int warp = tid >> 5, lane = tid & 31;
    if (lane == 0) {
        #pragma unroll
        for (int qi = 0; qi < 16; ++qi) sm[warp][qi] = v[qi];
    }
    __syncthreads();
    if (tid < 16) {
        double acc = 0.0;
        #pragma unroll
        for (int w = 0; w < 8; ++w) acc += sm[w][tid];
        g_part[blockIdx.x][tid] = acc;
    }
}

// ---------------------------------------------------------------------------
__global__ void k_solve_final(float* out) {
    int tid = threadIdx.x;   // 32 threads
    double v[16];
    #pragma unroll
    for (int qi = 0; qi < 16; ++qi) v[qi] = g_part[tid][qi];
    #pragma unroll
    for (int qi = 0; qi < 16; ++qi) {
        #pragma unroll
        for (int off = 16; off > 0; off >>= 1)
            v[qi] += __shfl_down_sync(0xffffffffu, v[qi], off);
    }
    if (tid != 0) return;

    const double N = (double)NPTS;
    double cAd[3] = {v[0]/N, v[1]/N, v[2]/N};
    double cBd[3] = {v[3]/N, v[4]/N, v[5]/N};
    float H[9], cA[3], cB[3];
    #pragma unroll
    for (int r = 0; r < 3; ++r) {
        cA[r] = (float)cAd[r]; cB[r] = (float)cBd[r];
        #pragma unroll
        for (int c = 0; c < 3; ++c)
            H[r*3+c] = (float)(v[6 + 3*r + c]/N - cAd[r]*cBd[c]);
    }
    float R[9], t[3];
    kabsch3(H, cA, cB, R, t);
    #pragma unroll
    for (int r = 0; r < 3; ++r) {
        out[r*4+0] = R[r*3+0]; out[r*4+1] = R[r*3+1];
        out[r*4+2] = R[r*3+2]; out[r*4+3] = t[r];
    }
    out[12] = 0.f; out[13] = 0.f; out[14] = 0.f; out[15] = 1.f;
}

// ---------------------------------------------------------------------------
extern "C" void kernel_launch(void* const* d_in, const int* in_sizes, int n_in,
                              void* d_out, int out_size) {
    const float* A = (const float*)d_in[0];
    const float* B = (const float*)d_in[1];
    float* out = (float*)d_out;

    k_prep<<<NPTS / 256, 256>>>(A, B);
    for (int it = 0; it < MAX_ITERS; ++it)
        k_nn<<<NN_BLOCKS, NN_TPB>>>();
    k_fred<<<FR_BLOCKS, 256>>>(A);
    k_solve_final<<<1, 32>>>(out);
}